// round 1
// baseline (speedup 1.0000x reference)
#include <cuda_runtime.h>
#include <cuda_fp16.h>
#include <cstdint>

#define TOK  2048
#define HID  2048
#define FFN  5632
#define NEXP 8

// ---------------- static scratch (no allocations allowed) ----------------
__device__ int   g_counts[NEXP];
__device__ int   g_lists[NEXP * TOK];
__device__ int   g_slot[TOK * 2];
__device__ float g_wt[TOK * 2];
__device__ __align__(16) __half g_xh[(size_t)TOK * HID];          // 8 MB
__device__ __align__(16) __half g_h[(size_t)NEXP * TOK * FFN];    // 184 MB
__device__ __align__(16) float  g_y[(size_t)NEXP * TOK * HID];    // 134 MB

// ---------------- helpers ----------------
__device__ __forceinline__ unsigned pack_h2(float a, float b) {
    __half2 h = __floats2half2_rn(a, b);
    return *reinterpret_cast<unsigned*>(&h);
}

__device__ __forceinline__ void mma16816(float* c, const unsigned* a, const unsigned* b) {
    asm volatile(
        "mma.sync.aligned.m16n8k16.row.col.f32.f16.f16.f32 "
        "{%0,%1,%2,%3},{%4,%5,%6,%7},{%8,%9},{%0,%1,%2,%3};\n"
        : "+f"(c[0]), "+f"(c[1]), "+f"(c[2]), "+f"(c[3])
        : "r"(a[0]), "r"(a[1]), "r"(a[2]), "r"(a[3]), "r"(b[0]), "r"(b[1]));
}

// ---------------- kernel 1: convert x to fp16 (+ zero expert counts) ----------------
__global__ void cvt_x_kernel(const float* __restrict__ x) {
    int v = blockIdx.x * blockDim.x + threadIdx.x;       // TOK*HID/4 threads
    if (blockIdx.x == 0 && threadIdx.x < NEXP) g_counts[threadIdx.x] = 0;
    float4 f = reinterpret_cast<const float4*>(x)[v];
    __half2 h0 = __floats2half2_rn(f.x, f.y);
    __half2 h1 = __floats2half2_rn(f.z, f.w);
    uint2 u;
    u.x = *reinterpret_cast<unsigned*>(&h0);
    u.y = *reinterpret_cast<unsigned*>(&h1);
    reinterpret_cast<uint2*>(g_xh)[v] = u;
}

// ---------------- kernel 2: router (1 warp per token, fp32) ----------------
__global__ void router_kernel(const float* __restrict__ x, const float* __restrict__ wg) {
    int gw   = (blockIdx.x * blockDim.x + threadIdx.x) >> 5;
    int lane = threadIdx.x & 31;
    if (gw >= TOK) return;
    const float* xr = x + (size_t)gw * HID;
    float acc[NEXP];
#pragma unroll
    for (int e = 0; e < NEXP; e++) acc[e] = 0.f;
    for (int h = lane; h < HID; h += 32) {
        float xv = xr[h];
#pragma unroll
        for (int e = 0; e < NEXP; e++) acc[e] += xv * wg[e * HID + h];
    }
#pragma unroll
    for (int e = 0; e < NEXP; e++) {
#pragma unroll
        for (int o = 16; o > 0; o >>= 1) acc[e] += __shfl_xor_sync(0xffffffffu, acc[e], o);
    }
    if (lane == 0) {
        float m = acc[0];
#pragma unroll
        for (int e = 1; e < NEXP; e++) m = fmaxf(m, acc[e]);
        float p[NEXP];
#pragma unroll
        for (int e = 0; e < NEXP; e++) p[e] = __expf(acc[e] - m);
        // top-2, lower index wins ties (matches jax.lax.top_k)
        int e0 = 0;
#pragma unroll
        for (int e = 1; e < NEXP; e++) if (p[e] > p[e0]) e0 = e;
        int e1 = (e0 == 0) ? 1 : 0;
#pragma unroll
        for (int e = 0; e < NEXP; e++) if (e != e0 && p[e] > p[e1]) e1 = e;
        float s  = p[e0] + p[e1];
        float w0 = p[e0] / s, w1 = p[e1] / s;
        int q0 = atomicAdd(&g_counts[e0], 1);
        int q1 = atomicAdd(&g_counts[e1], 1);
        g_lists[e0 * TOK + q0] = gw;
        g_lists[e1 * TOK + q1] = gw;
        g_slot[2 * gw]     = e0 * TOK + q0;  g_wt[2 * gw]     = w0;
        g_slot[2 * gw + 1] = e1 * TOK + q1;  g_wt[2 * gw + 1] = w1;
    }
}

// ---------------- kernel 3: GEMM1 — h = silu(x@w1^T) * (x@w3^T), fused ----------------
// Block tile: 128 tokens x 64 ffn cols, BK=64. B smem interleaves w1 (even rows)
// and w3 (odd rows) so each thread's mma C pair (c0,c1) is (w1-dot, w3-dot) for
// the SAME ffn column -> silu fuses locally with no shuffle.
__global__ __launch_bounds__(256, 1) void gemm13_kernel(const float* __restrict__ w1,
                                                        const float* __restrict__ w3) {
    const int e = blockIdx.z;
    const int cnt = g_counts[e];
    const int posBase = blockIdx.y * 128;
    if (posBase >= cnt) return;
    const int fBase = blockIdx.x * 64;

    __shared__ __half As[128][72];
    __shared__ __half Bs[128][72];

    const int tid = threadIdx.x;
    const int lane = tid & 31, warp = tid >> 5;
    const int wm = warp >> 1, wn = warp & 1;       // 4 x 2 warp grid, 32x64 each
    const int g = lane >> 2, t4 = lane & 3;

    const int arow = tid >> 1, ahalf = tid & 1;
    int ap = posBase + arow; if (ap > cnt - 1) ap = cnt - 1;
    const __half* aSrc = g_xh + (size_t)g_lists[e * TOK + ap] * HID + ahalf * 32;

    const int brow = tid >> 1, bhalf = tid & 1;
    const int f = fBase + (brow >> 1);
    const float* bSrc = ((brow & 1) ? w3 : w1) + ((size_t)e * FFN + f) * HID + bhalf * 32;

    float acc[2][8][4];
#pragma unroll
    for (int i = 0; i < 2; i++)
#pragma unroll
        for (int j = 0; j < 8; j++)
#pragma unroll
            for (int k = 0; k < 4; k++) acc[i][j][k] = 0.f;

    uint4 ra[4]; float4 rb[8];
#pragma unroll
    for (int j = 0; j < 4; j++) ra[j] = *reinterpret_cast<const uint4*>(aSrc + j * 8);
#pragma unroll
    for (int j = 0; j < 8; j++) rb[j] = *reinterpret_cast<const float4*>(bSrc + j * 4);

    for (int kt = 0; kt < HID; kt += 64) {
#pragma unroll
        for (int j = 0; j < 4; j++)
            *reinterpret_cast<uint4*>(&As[arow][ahalf * 32 + j * 8]) = ra[j];
#pragma unroll
        for (int j = 0; j < 4; j++) {
            uint4 u;
            u.x = pack_h2(rb[2 * j].x, rb[2 * j].y);
            u.y = pack_h2(rb[2 * j].z, rb[2 * j].w);
            u.z = pack_h2(rb[2 * j + 1].x, rb[2 * j + 1].y);
            u.w = pack_h2(rb[2 * j + 1].z, rb[2 * j + 1].w);
            *reinterpret_cast<uint4*>(&Bs[brow][bhalf * 32 + j * 8]) = u;
        }
        __syncthreads();
        if (kt + 64 < HID) {   // overlap next-tile LDG with this tile's MMAs
#pragma unroll
            for (int j = 0; j < 4; j++) ra[j] = *reinterpret_cast<const uint4*>(aSrc + kt + 64 + j * 8);
#pragma unroll
            for (int j = 0; j < 8; j++) rb[j] = *reinterpret_cast<const float4*>(bSrc + kt + 64 + j * 4);
        }
#pragma unroll
        for (int kk = 0; kk < 64; kk += 16) {
            unsigned a[2][4], b[8][2];
#pragma unroll
            for (int mf = 0; mf < 2; mf++) {
                int r0 = wm * 32 + mf * 16;
                a[mf][0] = *reinterpret_cast<const unsigned*>(&As[r0 + g][kk + 2 * t4]);
                a[mf][1] = *reinterpret_cast<const unsigned*>(&As[r0 + g + 8][kk + 2 * t4]);
                a[mf][2] = *reinterpret_cast<const unsigned*>(&As[r0 + g][kk + 2 * t4 + 8]);
                a[mf][3] = *reinterpret_cast<const unsigned*>(&As[r0 + g + 8][kk + 2 * t4 + 8]);
            }
#pragma unroll
            for (int nf = 0; nf < 8; nf++) {
                int n = wn * 64 + nf * 8 + g;
                b[nf][0] = *reinterpret_cast<const unsigned*>(&Bs[n][kk + 2 * t4]);
                b[nf][1] = *reinterpret_cast<const unsigned*>(&Bs[n][kk + 2 * t4 + 8]);
            }
#pragma unroll
            for (int mf = 0; mf < 2; mf++)
#pragma unroll
                for (int nf = 0; nf < 8; nf++) mma16816(acc[mf][nf], a[mf], b[nf]);
        }
        __syncthreads();
    }

    // fused silu(w1)*w3 epilogue -> fp16 h
#pragma unroll
    for (int mf = 0; mf < 2; mf++) {
#pragma unroll
        for (int nf = 0; nf < 8; nf++) {
            int r = wm * 32 + mf * 16 + g;
            int fc = fBase + wn * 32 + nf * 4 + t4;
            float* c = acc[mf][nf];
            int p0 = posBase + r, p1 = p0 + 8;
            if (p0 < cnt) {
                float s0 = c[0] / (1.f + __expf(-c[0]));
                g_h[(size_t)(e * TOK + p0) * FFN + fc] = __float2half(s0 * c[1]);
            }
            if (p1 < cnt) {
                float s1 = c[2] / (1.f + __expf(-c[2]));
                g_h[(size_t)(e * TOK + p1) * FFN + fc] = __float2half(s1 * c[3]);
            }
        }
    }
}

// ---------------- kernel 4: GEMM2 — y = h @ w2^T (per expert) ----------------
__global__ __launch_bounds__(256, 1) void gemm2_kernel(const float* __restrict__ w2) {
    const int e = blockIdx.z;
    const int cnt = g_counts[e];
    const int posBase = blockIdx.y * 128;
    if (posBase >= cnt) return;
    const int nBase = blockIdx.x * 128;

    __shared__ __half As[128][72];
    __shared__ __half Bs[128][72];

    const int tid = threadIdx.x;
    const int lane = tid & 31, warp = tid >> 5;
    const int wm = warp >> 1, wn = warp & 1;
    const int g = lane >> 2, t4 = lane & 3;

    const int arow = tid >> 1, ahalf = tid & 1;
    int ap = posBase + arow; if (ap > cnt - 1) ap = cnt - 1;
    const __half* aSrc = g_h + (size_t)(e * TOK + ap) * FFN + ahalf * 32;

    const int brow = tid >> 1, bhalf = tid & 1;
    const float* bSrc = w2 + ((size_t)e * HID + nBase + brow) * FFN + bhalf * 32;

    float acc[2][8][4];
#pragma unroll
    for (int i = 0; i < 2; i++)
#pragma unroll
        for (int j = 0; j < 8; j++)
#pragma unroll
            for (int k = 0; k < 4; k++) acc[i][j][k] = 0.f;

    uint4 ra[4]; float4 rb[8];
#pragma unroll
    for (int j = 0; j < 4; j++) ra[j] = *reinterpret_cast<const uint4*>(aSrc + j * 8);
#pragma unroll
    for (int j = 0; j < 8; j++) rb[j] = *reinterpret_cast<const float4*>(bSrc + j * 4);

    for (int kt = 0; kt < FFN; kt += 64) {
#pragma unroll
        for (int j = 0; j < 4; j++)
            *reinterpret_cast<uint4*>(&As[arow][ahalf * 32 + j * 8]) = ra[j];
#pragma unroll
        for (int j = 0; j < 4; j++) {
            uint4 u;
            u.x = pack_h2(rb[2 * j].x, rb[2 * j].y);
            u.y = pack_h2(rb[2 * j].z, rb[2 * j].w);
            u.z = pack_h2(rb[2 * j + 1].x, rb[2 * j + 1].y);
            u.w = pack_h2(rb[2 * j + 1].z, rb[2 * j + 1].w);
            *reinterpret_cast<uint4*>(&Bs[brow][bhalf * 32 + j * 8]) = u;
        }
        __syncthreads();
        if (kt + 64 < FFN) {
#pragma unroll
            for (int j = 0; j < 4; j++) ra[j] = *reinterpret_cast<const uint4*>(aSrc + kt + 64 + j * 8);
#pragma unroll
            for (int j = 0; j < 8; j++) rb[j] = *reinterpret_cast<const float4*>(bSrc + kt + 64 + j * 4);
        }
#pragma unroll
        for (int kk = 0; kk < 64; kk += 16) {
            unsigned a[2][4], b[8][2];
#pragma unroll
            for (int mf = 0; mf < 2; mf++) {
                int r0 = wm * 32 + mf * 16;
                a[mf][0] = *reinterpret_cast<const unsigned*>(&As[r0 + g][kk + 2 * t4]);
                a[mf][1] = *reinterpret_cast<const unsigned*>(&As[r0 + g + 8][kk + 2 * t4]);
                a[mf][2] = *reinterpret_cast<const unsigned*>(&As[r0 + g][kk + 2 * t4 + 8]);
                a[mf][3] = *reinterpret_cast<const unsigned*>(&As[r0 + g + 8][kk + 2 * t4 + 8]);
            }
#pragma unroll
            for (int nf = 0; nf < 8; nf++) {
                int n = wn * 64 + nf * 8 + g;
                b[nf][0] = *reinterpret_cast<const unsigned*>(&Bs[n][kk + 2 * t4]);
                b[nf][1] = *reinterpret_cast<const unsigned*>(&Bs[n][kk + 2 * t4 + 8]);
            }
#pragma unroll
            for (int mf = 0; mf < 2; mf++)
#pragma unroll
                for (int nf = 0; nf < 8; nf++) mma16816(acc[mf][nf], a[mf], b[nf]);
        }
        __syncthreads();
    }

#pragma unroll
    for (int mf = 0; mf < 2; mf++) {
#pragma unroll
        for (int nf = 0; nf < 8; nf++) {
            int r = wm * 32 + mf * 16 + g;
            int nc = nBase + wn * 64 + nf * 8 + 2 * t4;
            float* c = acc[mf][nf];
            int p0 = posBase + r, p1 = p0 + 8;
            if (p0 < cnt)
                *reinterpret_cast<float2*>(&g_y[(size_t)(e * TOK + p0) * HID + nc]) = make_float2(c[0], c[1]);
            if (p1 < cnt)
                *reinterpret_cast<float2*>(&g_y[(size_t)(e * TOK + p1) * HID + nc]) = make_float2(c[2], c[3]);
        }
    }
}

// ---------------- kernel 5: deterministic combine ----------------
__global__ void combine_kernel(float* __restrict__ out) {
    int v = blockIdx.x * blockDim.x + threadIdx.x;   // TOK*HID/4 threads
    int t  = v >> 9;                                  // HID/4 = 512 vec4 per token
    int dv = v & 511;
    float w0 = g_wt[2 * t], w1 = g_wt[2 * t + 1];
    int s0 = g_slot[2 * t], s1 = g_slot[2 * t + 1];
    float4 a = reinterpret_cast<const float4*>(g_y + (size_t)s0 * HID)[dv];
    float4 b = reinterpret_cast<const float4*>(g_y + (size_t)s1 * HID)[dv];
    float4 r;
    r.x = w0 * a.x + w1 * b.x;
    r.y = w0 * a.y + w1 * b.y;
    r.z = w0 * a.z + w1 * b.z;
    r.w = w0 * a.w + w1 * b.w;
    reinterpret_cast<float4*>(out)[v] = r;
}

// ---------------- launch ----------------
extern "C" void kernel_launch(void* const* d_in, const int* in_sizes, int n_in,
                              void* d_out, int out_size) {
    const float* x  = (const float*)d_in[0];   // hidden_states [2,1024,2048]
    const float* wg = (const float*)d_in[1];   // w_gate [8,2048]
    const float* w1 = (const float*)d_in[2];   // [8,5632,2048]
    const float* w2 = (const float*)d_in[3];   // [8,2048,5632]
    const float* w3 = (const float*)d_in[4];   // [8,5632,2048]
    float* out = (float*)d_out;

    cvt_x_kernel<<<(TOK * HID / 4) / 256, 256>>>(x);
    router_kernel<<<(TOK * 32) / 256, 256>>>(x, wg);
    gemm13_kernel<<<dim3(FFN / 64, TOK / 128, NEXP), 256>>>(w1, w3);
    gemm2_kernel<<<dim3(HID / 128, TOK / 128, NEXP), 256>>>(w2);
    combine_kernel<<<(TOK * HID / 4) / 256, 256>>>(out);
}

// round 2
// speedup vs baseline: 1.6779x; 1.6779x over previous
#include <cuda_runtime.h>
#include <cuda_fp16.h>
#include <cstdint>

#define TOK  2048
#define HID  2048
#define FFN  5632
#define NEXP 8

// ---------------- static scratch ----------------
__device__ int   g_counts[NEXP];
__device__ int   g_lists[NEXP * TOK];
__device__ int   g_slot[TOK * 2];
__device__ float g_wt[TOK * 2];
__device__ __align__(16) __half g_xh[(size_t)TOK * HID];                  // 8 MB
__device__ __align__(16) __half g_w13h[(size_t)NEXP * FFN * 2 * HID];     // 369 MB (w1/w3 interleaved rows)
__device__ __align__(16) __half g_w2h[(size_t)NEXP * HID * FFN];          // 184 MB
__device__ __align__(16) __half g_h[(size_t)NEXP * TOK * FFN];            // 184 MB
__device__ __align__(16) float  g_y[(size_t)NEXP * TOK * HID];            // 134 MB

// ---------------- helpers ----------------
__device__ __forceinline__ void mma16816(float* c, const unsigned* a, const unsigned* b) {
    asm volatile(
        "mma.sync.aligned.m16n8k16.row.col.f32.f16.f16.f32 "
        "{%0,%1,%2,%3},{%4,%5,%6,%7},{%8,%9},{%0,%1,%2,%3};\n"
        : "+f"(c[0]), "+f"(c[1]), "+f"(c[2]), "+f"(c[3])
        : "r"(a[0]), "r"(a[1]), "r"(a[2]), "r"(a[3]), "r"(b[0]), "r"(b[1]));
}

__device__ __forceinline__ void ldsm4(unsigned& r0, unsigned& r1, unsigned& r2, unsigned& r3,
                                      unsigned addr) {
    asm volatile("ldmatrix.sync.aligned.m8n8.x4.shared.b16 {%0,%1,%2,%3}, [%4];"
                 : "=r"(r0), "=r"(r1), "=r"(r2), "=r"(r3) : "r"(addr));
}

__device__ __forceinline__ void cpa16(unsigned dst, const void* src) {
    asm volatile("cp.async.cg.shared.global [%0], [%1], 16;" :: "r"(dst), "l"(src));
}
__device__ __forceinline__ void cpa_commit() { asm volatile("cp.async.commit_group;"); }
__device__ __forceinline__ void cpa_wait1()  { asm volatile("cp.async.wait_group 1;"); }
__device__ __forceinline__ void cpa_wait0()  { asm volatile("cp.async.wait_group 0;"); }

// ---------------- kernel 0a: weights w1/w3 -> fp16, interleaved rows ----------------
// dst row r (of 2*FFN) within expert e: f=r>>1, (r&1)? w3 : w1
__global__ void conv_w13_kernel(const float* __restrict__ w1, const float* __restrict__ w3) {
    int e = blockIdx.z;
    int v = blockIdx.x * blockDim.x + threadIdx.x;     // (2*FFN)*(HID/8) threads per expert
    int rr = v >> 8;                                   // HID/8 = 256 chunks per row
    int c8 = (v & 255) * 8;
    int f = rr >> 1;
    const float* src = ((rr & 1) ? w3 : w1) + ((size_t)e * FFN + f) * HID + c8;
    float4 f0 = reinterpret_cast<const float4*>(src)[0];
    float4 f1 = reinterpret_cast<const float4*>(src)[1];
    __half2 h0 = __floats2half2_rn(f0.x, f0.y);
    __half2 h1 = __floats2half2_rn(f0.z, f0.w);
    __half2 h2 = __floats2half2_rn(f1.x, f1.y);
    __half2 h3 = __floats2half2_rn(f1.z, f1.w);
    uint4 u;
    u.x = *reinterpret_cast<unsigned*>(&h0);
    u.y = *reinterpret_cast<unsigned*>(&h1);
    u.z = *reinterpret_cast<unsigned*>(&h2);
    u.w = *reinterpret_cast<unsigned*>(&h3);
    *reinterpret_cast<uint4*>(g_w13h + ((size_t)e * FFN * 2 + rr) * HID + c8) = u;
}

// ---------------- kernel 0b: w2 -> fp16 ----------------
__global__ void conv_w2_kernel(const float* __restrict__ w2) {
    int e = blockIdx.z;
    int v = blockIdx.x * blockDim.x + threadIdx.x;     // HID*(FFN/8) threads per expert
    int row = v / (FFN / 8);
    int c8 = (v % (FFN / 8)) * 8;
    const float* src = w2 + ((size_t)e * HID + row) * FFN + c8;
    float4 f0 = reinterpret_cast<const float4*>(src)[0];
    float4 f1 = reinterpret_cast<const float4*>(src)[1];
    __half2 h0 = __floats2half2_rn(f0.x, f0.y);
    __half2 h1 = __floats2half2_rn(f0.z, f0.w);
    __half2 h2 = __floats2half2_rn(f1.x, f1.y);
    __half2 h3 = __floats2half2_rn(f1.z, f1.w);
    uint4 u;
    u.x = *reinterpret_cast<unsigned*>(&h0);
    u.y = *reinterpret_cast<unsigned*>(&h1);
    u.z = *reinterpret_cast<unsigned*>(&h2);
    u.w = *reinterpret_cast<unsigned*>(&h3);
    *reinterpret_cast<uint4*>(g_w2h + ((size_t)e * HID + row) * FFN + c8) = u;
}

// ---------------- kernel 1: convert x to fp16 (+ zero expert counts) ----------------
__global__ void cvt_x_kernel(const float* __restrict__ x) {
    int v = blockIdx.x * blockDim.x + threadIdx.x;
    if (blockIdx.x == 0 && threadIdx.x < NEXP) g_counts[threadIdx.x] = 0;
    float4 f = reinterpret_cast<const float4*>(x)[v];
    __half2 h0 = __floats2half2_rn(f.x, f.y);
    __half2 h1 = __floats2half2_rn(f.z, f.w);
    uint2 u;
    u.x = *reinterpret_cast<unsigned*>(&h0);
    u.y = *reinterpret_cast<unsigned*>(&h1);
    reinterpret_cast<uint2*>(g_xh)[v] = u;
}

// ---------------- kernel 2: router (1 warp per token, fp32) ----------------
__global__ void router_kernel(const float* __restrict__ x, const float* __restrict__ wg) {
    int gw   = (blockIdx.x * blockDim.x + threadIdx.x) >> 5;
    int lane = threadIdx.x & 31;
    if (gw >= TOK) return;
    const float* xr = x + (size_t)gw * HID;
    float acc[NEXP];
#pragma unroll
    for (int e = 0; e < NEXP; e++) acc[e] = 0.f;
    for (int h = lane; h < HID; h += 32) {
        float xv = xr[h];
#pragma unroll
        for (int e = 0; e < NEXP; e++) acc[e] += xv * wg[e * HID + h];
    }
#pragma unroll
    for (int e = 0; e < NEXP; e++) {
#pragma unroll
        for (int o = 16; o > 0; o >>= 1) acc[e] += __shfl_xor_sync(0xffffffffu, acc[e], o);
    }
    if (lane == 0) {
        float m = acc[0];
#pragma unroll
        for (int e = 1; e < NEXP; e++) m = fmaxf(m, acc[e]);
        float p[NEXP];
#pragma unroll
        for (int e = 0; e < NEXP; e++) p[e] = __expf(acc[e] - m);
        int e0 = 0;
#pragma unroll
        for (int e = 1; e < NEXP; e++) if (p[e] > p[e0]) e0 = e;
        int e1 = (e0 == 0) ? 1 : 0;
#pragma unroll
        for (int e = 0; e < NEXP; e++) if (e != e0 && p[e] > p[e1]) e1 = e;
        float s  = p[e0] + p[e1];
        float w0 = p[e0] / s, w1 = p[e1] / s;
        int q0 = atomicAdd(&g_counts[e0], 1);
        int q1 = atomicAdd(&g_counts[e1], 1);
        g_lists[e0 * TOK + q0] = gw;
        g_lists[e1 * TOK + q1] = gw;
        g_slot[2 * gw]     = e0 * TOK + q0;  g_wt[2 * gw]     = w0;
        g_slot[2 * gw + 1] = e1 * TOK + q1;  g_wt[2 * gw + 1] = w1;
    }
}

// ============ shared GEMM machinery: 128(M) x 128(Nsmem) x 64(K) tile, 2-stage ============
// smem: As[2][128][64], Bs[2][128][64] halves, XOR-swizzled 16B chunks.
#define STG_H   8192                       // halves per stage per matrix
#define SMEM_BYTES (4 * STG_H * 2)         // 64 KB

// ---------------- kernel 3: GEMM1 fused silu ----------------
__global__ __launch_bounds__(256, 2) void gemm13_kernel() {
    const int e = blockIdx.z;
    const int cnt = g_counts[e];
    const int posBase = blockIdx.y * 128;
    if (posBase >= cnt) return;
    const int fBase = blockIdx.x * 64;

    extern __shared__ __half smem[];
    const unsigned smemBase = (unsigned)__cvta_generic_to_shared(smem);

    const int tid = threadIdx.x;
    const int lane = tid & 31, warp = tid >> 5;
    const int wm = warp >> 1, wn = warp & 1;
    const int g = lane >> 2, t4 = lane & 3;

    // ---- staging pointers (per-thread row) ----
    const int srow = tid >> 1;            // 0..127
    const int hs   = tid & 1;             // chunk base hs*4
    int ap = posBase + srow; if (ap > cnt - 1) ap = cnt - 1;
    const __half* aPtr = g_xh + (size_t)g_lists[e * TOK + ap] * HID;
    const __half* bPtr = g_w13h + ((size_t)e * FFN * 2 + fBase * 2 + srow) * HID;
    unsigned dstOffA[4], dstOffB[4];
#pragma unroll
    for (int j = 0; j < 4; j++) {
        int ck = hs * 4 + j;
        unsigned sw = (unsigned)((ck ^ (srow & 7)) * 8);
        dstOffA[j] = (unsigned)(srow * 64) + sw;
        dstOffB[j] = dstOffA[j];
    }

    // ---- fragment address precompute ----
    const int laneK  = lane >> 4;           // 0/1
    const int laneKB = (lane >> 3) & 1;
    const int rx     = lane & 7;
    unsigned offA[2], offB[4];
#pragma unroll
    for (int mf = 0; mf < 2; mf++) offA[mf] = (unsigned)((wm * 32 + mf * 16 + (lane & 15)) * 64);
#pragma unroll
    for (int np = 0; np < 4; np++)
        offB[np] = (unsigned)((wn * 64 + np * 16 + (lane & 7) + ((lane >> 4) << 3)) * 64);

    float acc[2][8][4];
#pragma unroll
    for (int i = 0; i < 2; i++)
#pragma unroll
        for (int j = 0; j < 8; j++)
#pragma unroll
            for (int k = 0; k < 4; k++) acc[i][j][k] = 0.f;

    // ---- prologue ----
#pragma unroll
    for (int j = 0; j < 4; j++) {
        int ck = hs * 4 + j;
        cpa16(smemBase + (dstOffA[j] << 1), aPtr + ck * 8);
        cpa16(smemBase + ((2 * STG_H + dstOffB[j]) << 1), bPtr + ck * 8);
    }
    cpa_commit();

    const int NT = HID / 64;   // 32
    for (int it = 0; it < NT; it++) {
        const int cur = it & 1;
        if (it + 1 < NT) {
            const int nxt = (it + 1) & 1;
            const int kt = (it + 1) * 64;
#pragma unroll
            for (int j = 0; j < 4; j++) {
                int ck = hs * 4 + j;
                cpa16(smemBase + ((nxt * STG_H + dstOffA[j]) << 1), aPtr + kt + ck * 8);
                cpa16(smemBase + (((2 + nxt) * STG_H + dstOffB[j]) << 1), bPtr + kt + ck * 8);
            }
            cpa_commit();
            cpa_wait1();
        } else {
            cpa_wait0();
        }
        __syncthreads();

        const unsigned aStage = smemBase + ((cur * STG_H) << 1);
        const unsigned bStage = smemBase + (((2 + cur) * STG_H) << 1);
#pragma unroll
        for (int ks = 0; ks < 4; ks++) {
            const int cb = ks * 2;
            unsigned a[2][4], b[8][2];
#pragma unroll
            for (int mf = 0; mf < 2; mf++) {
                unsigned ad = aStage + ((offA[mf] + (unsigned)(((cb + laneK) ^ rx) * 8)) << 1);
                ldsm4(a[mf][0], a[mf][1], a[mf][2], a[mf][3], ad);
            }
#pragma unroll
            for (int np = 0; np < 4; np++) {
                unsigned ad = bStage + ((offB[np] + (unsigned)(((cb + laneKB) ^ rx) * 8)) << 1);
                ldsm4(b[2 * np][0], b[2 * np][1], b[2 * np + 1][0], b[2 * np + 1][1], ad);
            }
#pragma unroll
            for (int mf = 0; mf < 2; mf++)
#pragma unroll
                for (int nf = 0; nf < 8; nf++) mma16816(acc[mf][nf], a[mf], b[nf]);
        }
        __syncthreads();
    }

    // ---- fused silu(w1)*w3 epilogue ----
#pragma unroll
    for (int mf = 0; mf < 2; mf++) {
#pragma unroll
        for (int nf = 0; nf < 8; nf++) {
            int r = wm * 32 + mf * 16 + g;
            int fc = fBase + wn * 32 + nf * 4 + t4;
            float* c = acc[mf][nf];
            int p0 = posBase + r, p1 = p0 + 8;
            if (p0 < cnt) {
                float s0 = c[0] / (1.f + __expf(-c[0]));
                g_h[(size_t)(e * TOK + p0) * FFN + fc] = __float2half(s0 * c[1]);
            }
            if (p1 < cnt) {
                float s1 = c[2] / (1.f + __expf(-c[2]));
                g_h[(size_t)(e * TOK + p1) * FFN + fc] = __float2half(s1 * c[3]);
            }
        }
    }
}

// ---------------- kernel 4: GEMM2 ----------------
__global__ __launch_bounds__(256, 2) void gemm2_kernel() {
    const int e = blockIdx.z;
    const int cnt = g_counts[e];
    const int posBase = blockIdx.y * 128;
    if (posBase >= cnt) return;
    const int nBase = blockIdx.x * 128;

    extern __shared__ __half smem[];
    const unsigned smemBase = (unsigned)__cvta_generic_to_shared(smem);

    const int tid = threadIdx.x;
    const int lane = tid & 31, warp = tid >> 5;
    const int wm = warp >> 1, wn = warp & 1;
    const int g = lane >> 2, t4 = lane & 3;

    const int srow = tid >> 1;
    const int hs   = tid & 1;
    int ap = posBase + srow; if (ap > cnt - 1) ap = cnt - 1;
    const __half* aPtr = g_h + (size_t)(e * TOK + ap) * FFN;
    const __half* bPtr = g_w2h + ((size_t)e * HID + nBase + srow) * FFN;
    unsigned dstOff[4];
#pragma unroll
    for (int j = 0; j < 4; j++) {
        int ck = hs * 4 + j;
        dstOff[j] = (unsigned)(srow * 64) + (unsigned)((ck ^ (srow & 7)) * 8);
    }

    const int laneK  = lane >> 4;
    const int laneKB = (lane >> 3) & 1;
    const int rx     = lane & 7;
    unsigned offA[2], offB[4];
#pragma unroll
    for (int mf = 0; mf < 2; mf++) offA[mf] = (unsigned)((wm * 32 + mf * 16 + (lane & 15)) * 64);
#pragma unroll
    for (int np = 0; np < 4; np++)
        offB[np] = (unsigned)((wn * 64 + np * 16 + (lane & 7) + ((lane >> 4) << 3)) * 64);

    float acc[2][8][4];
#pragma unroll
    for (int i = 0; i < 2; i++)
#pragma unroll
        for (int j = 0; j < 8; j++)
#pragma unroll
            for (int k = 0; k < 4; k++) acc[i][j][k] = 0.f;

#pragma unroll
    for (int j = 0; j < 4; j++) {
        int ck = hs * 4 + j;
        cpa16(smemBase + (dstOff[j] << 1), aPtr + ck * 8);
        cpa16(smemBase + ((2 * STG_H + dstOff[j]) << 1), bPtr + ck * 8);
    }
    cpa_commit();

    const int NT = FFN / 64;   // 88
    for (int it = 0; it < NT; it++) {
        const int cur = it & 1;
        if (it + 1 < NT) {
            const int nxt = (it + 1) & 1;
            const int kt = (it + 1) * 64;
#pragma unroll
            for (int j = 0; j < 4; j++) {
                int ck = hs * 4 + j;
                cpa16(smemBase + ((nxt * STG_H + dstOff[j]) << 1), aPtr + kt + ck * 8);
                cpa16(smemBase + (((2 + nxt) * STG_H + dstOff[j]) << 1), bPtr + kt + ck * 8);
            }
            cpa_commit();
            cpa_wait1();
        } else {
            cpa_wait0();
        }
        __syncthreads();

        const unsigned aStage = smemBase + ((cur * STG_H) << 1);
        const unsigned bStage = smemBase + (((2 + cur) * STG_H) << 1);
#pragma unroll
        for (int ks = 0; ks < 4; ks++) {
            const int cb = ks * 2;
            unsigned a[2][4], b[8][2];
#pragma unroll
            for (int mf = 0; mf < 2; mf++) {
                unsigned ad = aStage + ((offA[mf] + (unsigned)(((cb + laneK) ^ rx) * 8)) << 1);
                ldsm4(a[mf][0], a[mf][1], a[mf][2], a[mf][3], ad);
            }
#pragma unroll
            for (int np = 0; np < 4; np++) {
                unsigned ad = bStage + ((offB[np] + (unsigned)(((cb + laneKB) ^ rx) * 8)) << 1);
                ldsm4(b[2 * np][0], b[2 * np][1], b[2 * np + 1][0], b[2 * np + 1][1], ad);
            }
#pragma unroll
            for (int mf = 0; mf < 2; mf++)
#pragma unroll
                for (int nf = 0; nf < 8; nf++) mma16816(acc[mf][nf], a[mf], b[nf]);
        }
        __syncthreads();
    }

#pragma unroll
    for (int mf = 0; mf < 2; mf++) {
#pragma unroll
        for (int nf = 0; nf < 8; nf++) {
            int r = wm * 32 + mf * 16 + g;
            int nc = nBase + wn * 64 + nf * 8 + 2 * t4;
            float* c = acc[mf][nf];
            int p0 = posBase + r, p1 = p0 + 8;
            if (p0 < cnt)
                *reinterpret_cast<float2*>(&g_y[(size_t)(e * TOK + p0) * HID + nc]) = make_float2(c[0], c[1]);
            if (p1 < cnt)
                *reinterpret_cast<float2*>(&g_y[(size_t)(e * TOK + p1) * HID + nc]) = make_float2(c[2], c[3]);
        }
    }
}

// ---------------- kernel 5: deterministic combine ----------------
__global__ void combine_kernel(float* __restrict__ out) {
    int v = blockIdx.x * blockDim.x + threadIdx.x;
    int t  = v >> 9;
    int dv = v & 511;
    float w0 = g_wt[2 * t], w1 = g_wt[2 * t + 1];
    int s0 = g_slot[2 * t], s1 = g_slot[2 * t + 1];
    float4 a = reinterpret_cast<const float4*>(g_y + (size_t)s0 * HID)[dv];
    float4 b = reinterpret_cast<const float4*>(g_y + (size_t)s1 * HID)[dv];
    float4 r;
    r.x = w0 * a.x + w1 * b.x;
    r.y = w0 * a.y + w1 * b.y;
    r.z = w0 * a.z + w1 * b.z;
    r.w = w0 * a.w + w1 * b.w;
    reinterpret_cast<float4*>(out)[v] = r;
}

// ---------------- launch ----------------
extern "C" void kernel_launch(void* const* d_in, const int* in_sizes, int n_in,
                              void* d_out, int out_size) {
    const float* x  = (const float*)d_in[0];
    const float* wg = (const float*)d_in[1];
    const float* w1 = (const float*)d_in[2];
    const float* w2 = (const float*)d_in[3];
    const float* w3 = (const float*)d_in[4];
    float* out = (float*)d_out;

    static bool attr_set = false;
    if (!attr_set) {
        cudaFuncSetAttribute(gemm13_kernel, cudaFuncAttributeMaxDynamicSharedMemorySize, SMEM_BYTES);
        cudaFuncSetAttribute(gemm2_kernel,  cudaFuncAttributeMaxDynamicSharedMemorySize, SMEM_BYTES);
        attr_set = true;
    }

    conv_w13_kernel<<<dim3(FFN * 2 * (HID / 8) / 256, 1, NEXP), 256>>>(w1, w3);
    conv_w2_kernel<<<dim3(HID * (FFN / 8) / 256, 1, NEXP), 256>>>(w2);
    cvt_x_kernel<<<(TOK * HID / 4) / 256, 256>>>(x);
    router_kernel<<<(TOK * 32) / 256, 256>>>(x, wg);
    gemm13_kernel<<<dim3(FFN / 64, TOK / 128, NEXP), 256, SMEM_BYTES>>>();
    gemm2_kernel<<<dim3(HID / 128, TOK / 128, NEXP), 256, SMEM_BYTES>>>();
    combine_kernel<<<(TOK * HID / 4) / 256, 256>>>(out);
}

// round 5
// speedup vs baseline: 4.2297x; 2.5208x over previous
#include <cuda_runtime.h>
#include <cuda.h>
#include <cuda_fp16.h>
#include <cstdint>

#define TOK  2048
#define HID  2048
#define FFN  5632
#define NEXP 8
#define NSTG 4
#define STAGE_BYTES 49152           // A 16KB + B 32KB
#define SMEM_REQ (1024 + NSTG * STAGE_BYTES + 128)

// ---- arch feature gate: tcgen05 only exists on sm_103a / sm_100a-class targets ----
#if !defined(__CUDA_ARCH__)
#  define TC_OK 1
#elif defined(__CUDA_ARCH_FEAT_SM103_ALL) || defined(__CUDA_ARCH_FEAT_SM100_ALL) || \
      defined(__CUDA_ARCH_FEAT_SM101_ALL) || \
      (defined(__CUDA_ARCH_SPECIFIC__) && (__CUDA_ARCH_SPECIFIC__ >= 1000)) || \
      (defined(__CUDA_ARCH_FAMILY_SPECIFIC__) && (__CUDA_ARCH_FAMILY_SPECIFIC__ >= 1000))
#  define TC_OK 1
#else
#  define TC_OK 0
#endif

// ---------------- static scratch ----------------
__device__ int   g_counts[NEXP];
__device__ int   g_lists[NEXP * TOK];
__device__ int   g_slot[TOK * 2];
__device__ float g_wt[TOK * 2];
__device__ __align__(1024) __half g_xg[(size_t)NEXP * TOK * HID];          // 64 MB gathered tokens
__device__ __align__(1024) __half g_w13h[(size_t)NEXP * FFN * 2 * HID];    // 369 MB interleaved w1/w3
__device__ __align__(1024) __half g_w2h[(size_t)NEXP * HID * FFN];         // 184 MB
__device__ __align__(1024) __half g_h[(size_t)NEXP * TOK * FFN];           // 184 MB
__device__ __align__(1024) float  g_y[(size_t)NEXP * TOK * HID];           // 134 MB

// ---------------- PTX helpers (generic) ----------------
__device__ __forceinline__ uint32_t smem_u32(const void* p) {
    uint32_t a;
    asm("{ .reg .u64 t; cvta.to.shared.u64 t, %1; cvt.u32.u64 %0, t; }" : "=r"(a) : "l"(p));
    return a;
}
__device__ __forceinline__ void mbar_init(uint32_t a, uint32_t cnt) {
    asm volatile("mbarrier.init.shared.b64 [%0], %1;" :: "r"(a), "r"(cnt) : "memory");
}
__device__ __forceinline__ void mbar_expect_tx(uint32_t a, uint32_t bytes) {
    asm volatile("mbarrier.arrive.expect_tx.shared.b64 _, [%0], %1;" :: "r"(a), "r"(bytes) : "memory");
}
__device__ __forceinline__ void mbar_wait(uint32_t a, uint32_t phase) {
    uint32_t done;
    asm volatile(
        "{\n\t.reg .pred p;\n\t"
        "mbarrier.try_wait.parity.acquire.cta.shared::cta.b64 p, [%1], %2;\n\t"
        "selp.b32 %0, 1, 0, p;\n\t}"
        : "=r"(done) : "r"(a), "r"(phase) : "memory");
    if (!done) {
        asm volatile(
            "{\n\t.reg .pred P1;\n\t"
            "W_%=:\n\t"
            "mbarrier.try_wait.parity.acquire.cta.shared::cta.b64 P1, [%0], %1, 0x989680;\n\t"
            "@P1 bra.uni D_%=;\n\t"
            "bra.uni W_%=;\n\t"
            "D_%=:\n\t}"
            :: "r"(a), "r"(phase) : "memory");
    }
}
__device__ __forceinline__ void tma3(uint32_t smem_dst, const CUtensorMap* tm,
                                     int cx, int cy, int cz, uint32_t mbar) {
    asm volatile(
        "cp.async.bulk.tensor.3d.shared::cta.global.tile.mbarrier::complete_tx::bytes "
        "[%0], [%1, {%2, %3, %4}], [%5];"
        :: "r"(smem_dst), "l"(tm), "r"(cx), "r"(cy), "r"(cz), "r"(mbar) : "memory");
}

// ---------------- tcgen05 helpers (only referenced from TC_OK code) ----------------
__device__ __forceinline__ void tc_alloc(uint32_t smem_result, uint32_t ncols) {
    asm volatile("tcgen05.alloc.cta_group::1.sync.aligned.shared::cta.b32 [%0], %1;"
                 :: "r"(smem_result), "r"(ncols) : "memory");
}
__device__ __forceinline__ void tc_dealloc(uint32_t tmem, uint32_t ncols) {
    asm volatile("tcgen05.dealloc.cta_group::1.sync.aligned.b32 %0, %1;" :: "r"(tmem), "r"(ncols));
}
__device__ __forceinline__ void tc_commit(uint32_t mbar) {
    asm volatile("tcgen05.commit.cta_group::1.mbarrier::arrive::one.shared::cluster.b64 [%0];"
                 :: "r"(mbar) : "memory");
}
__device__ __forceinline__ void tc_fence_after() {
    asm volatile("tcgen05.fence::after_thread_sync;" ::: "memory");
}
__device__ __forceinline__ void tc_fence_before() {
    asm volatile("tcgen05.fence::before_thread_sync;" ::: "memory");
}
__device__ __forceinline__ void tc_wait_ld() {
    asm volatile("tcgen05.wait::ld.sync.aligned;" ::: "memory");
}
__device__ __forceinline__ void mma_f16_ss(uint32_t d, uint64_t ad, uint64_t bd,
                                           uint32_t idesc, uint32_t en) {
    asm volatile(
        "{\n\t.reg .pred p;\n\t"
        "setp.ne.u32 p, %4, 0;\n\t"
        "tcgen05.mma.cta_group::1.kind::f16 [%0], %1, %2, %3, {%5, %5, %5, %5}, p;\n\t}"
        :: "r"(d), "l"(ad), "l"(bd), "r"(idesc), "r"(en), "r"(0u) : "memory");
}
#define LDTM32(r, addr) \
    asm volatile("tcgen05.ld.sync.aligned.32x32b.x32.b32 " \
        "{%0,%1,%2,%3,%4,%5,%6,%7,%8,%9,%10,%11,%12,%13,%14,%15," \
        "%16,%17,%18,%19,%20,%21,%22,%23,%24,%25,%26,%27,%28,%29,%30,%31}, [%32];" \
        : "=r"((r)[0]),"=r"((r)[1]),"=r"((r)[2]),"=r"((r)[3]),"=r"((r)[4]),"=r"((r)[5]), \
          "=r"((r)[6]),"=r"((r)[7]),"=r"((r)[8]),"=r"((r)[9]),"=r"((r)[10]),"=r"((r)[11]), \
          "=r"((r)[12]),"=r"((r)[13]),"=r"((r)[14]),"=r"((r)[15]),"=r"((r)[16]),"=r"((r)[17]), \
          "=r"((r)[18]),"=r"((r)[19]),"=r"((r)[20]),"=r"((r)[21]),"=r"((r)[22]),"=r"((r)[23]), \
          "=r"((r)[24]),"=r"((r)[25]),"=r"((r)[26]),"=r"((r)[27]),"=r"((r)[28]),"=r"((r)[29]), \
          "=r"((r)[30]),"=r"((r)[31]) : "r"(addr))

static constexpr uint64_t DESC_BASE_SW128 =
    (uint64_t(2) << 61) | (uint64_t(1) << 46) | (uint64_t(64) << 32) | (uint64_t(1) << 16);
__device__ __forceinline__ uint64_t smem_desc(uint32_t addr) {
    return DESC_BASE_SW128 | ((uint64_t)(addr >> 4) & 0x3FFF);
}
// idesc: fp32 accum (bit4), F16 a/b (0), N=256 -> 32<<17, M=128 -> 8<<24
#define IDESC ((1u << 4) | (32u << 17) | (8u << 24))

// ---------------- small kernels ----------------
__global__ void zero_counts_kernel() { if (threadIdx.x < NEXP) g_counts[threadIdx.x] = 0; }

__global__ void conv_w13_kernel(const float* __restrict__ w1, const float* __restrict__ w3) {
    int e = blockIdx.z;
    int v = blockIdx.x * blockDim.x + threadIdx.x;
    int rr = v >> 8;
    int c8 = (v & 255) * 8;
    int f = rr >> 1;
    const float* src = ((rr & 1) ? w3 : w1) + ((size_t)e * FFN + f) * HID + c8;
    float4 f0 = reinterpret_cast<const float4*>(src)[0];
    float4 f1 = reinterpret_cast<const float4*>(src)[1];
    __half2 h0 = __floats2half2_rn(f0.x, f0.y), h1 = __floats2half2_rn(f0.z, f0.w);
    __half2 h2 = __floats2half2_rn(f1.x, f1.y), h3 = __floats2half2_rn(f1.z, f1.w);
    uint4 u = { *(unsigned*)&h0, *(unsigned*)&h1, *(unsigned*)&h2, *(unsigned*)&h3 };
    *reinterpret_cast<uint4*>(g_w13h + ((size_t)e * FFN * 2 + rr) * HID + c8) = u;
}

__global__ void conv_w2_kernel(const float* __restrict__ w2) {
    int e = blockIdx.z;
    int v = blockIdx.x * blockDim.x + threadIdx.x;
    int row = v / (FFN / 8);
    int c8 = (v % (FFN / 8)) * 8;
    const float* src = w2 + ((size_t)e * HID + row) * FFN + c8;
    float4 f0 = reinterpret_cast<const float4*>(src)[0];
    float4 f1 = reinterpret_cast<const float4*>(src)[1];
    __half2 h0 = __floats2half2_rn(f0.x, f0.y), h1 = __floats2half2_rn(f0.z, f0.w);
    __half2 h2 = __floats2half2_rn(f1.x, f1.y), h3 = __floats2half2_rn(f1.z, f1.w);
    uint4 u = { *(unsigned*)&h0, *(unsigned*)&h1, *(unsigned*)&h2, *(unsigned*)&h3 };
    *reinterpret_cast<uint4*>(g_w2h + ((size_t)e * HID + row) * FFN + c8) = u;
}

__global__ void router_kernel(const float* __restrict__ x, const float* __restrict__ wg) {
    int gw   = (blockIdx.x * blockDim.x + threadIdx.x) >> 5;
    int lane = threadIdx.x & 31;
    if (gw >= TOK) return;
    const float* xr = x + (size_t)gw * HID;
    float acc[NEXP];
#pragma unroll
    for (int e = 0; e < NEXP; e++) acc[e] = 0.f;
    for (int h = lane; h < HID; h += 32) {
        float xv = xr[h];
#pragma unroll
        for (int e = 0; e < NEXP; e++) acc[e] += xv * wg[e * HID + h];
    }
#pragma unroll
    for (int e = 0; e < NEXP; e++) {
#pragma unroll
        for (int o = 16; o > 0; o >>= 1) acc[e] += __shfl_xor_sync(0xffffffffu, acc[e], o);
    }
    if (lane == 0) {
        float m = acc[0];
#pragma unroll
        for (int e = 1; e < NEXP; e++) m = fmaxf(m, acc[e]);
        float p[NEXP];
#pragma unroll
        for (int e = 0; e < NEXP; e++) p[e] = __expf(acc[e] - m);
        int e0 = 0;
#pragma unroll
        for (int e = 1; e < NEXP; e++) if (p[e] > p[e0]) e0 = e;
        int e1 = (e0 == 0) ? 1 : 0;
#pragma unroll
        for (int e = 0; e < NEXP; e++) if (e != e0 && p[e] > p[e1]) e1 = e;
        float s  = p[e0] + p[e1];
        float w0 = p[e0] / s, w1 = p[e1] / s;
        int q0 = atomicAdd(&g_counts[e0], 1);
        int q1 = atomicAdd(&g_counts[e1], 1);
        g_lists[e0 * TOK + q0] = gw;
        g_lists[e1 * TOK + q1] = gw;
        g_slot[2 * gw]     = e0 * TOK + q0;  g_wt[2 * gw]     = w0;
        g_slot[2 * gw + 1] = e1 * TOK + q1;  g_wt[2 * gw + 1] = w1;
    }
}

// gather routed tokens -> contiguous fp16 per-expert rows (zero pad to 128)
__global__ void gather_kernel(const float* __restrict__ x) {
    int e = blockIdx.y, pos = blockIdx.x;
    int cnt = g_counts[e];
    int cc = (cnt + 127) & ~127;
    if (pos >= cc) return;
    __half* dst = g_xg + ((size_t)e * TOK + pos) * HID;
    int t8 = threadIdx.x;
    if (pos < cnt) {
        const float* src = x + (size_t)g_lists[e * TOK + pos] * HID + t8 * 8;
        float4 f0 = reinterpret_cast<const float4*>(src)[0];
        float4 f1 = reinterpret_cast<const float4*>(src)[1];
        __half2 h0 = __floats2half2_rn(f0.x, f0.y), h1 = __floats2half2_rn(f0.z, f0.w);
        __half2 h2 = __floats2half2_rn(f1.x, f1.y), h3 = __floats2half2_rn(f1.z, f1.w);
        uint4 u = { *(unsigned*)&h0, *(unsigned*)&h1, *(unsigned*)&h2, *(unsigned*)&h3 };
        *reinterpret_cast<uint4*>(dst + t8 * 8) = u;
    } else {
        uint4 z = {0u, 0u, 0u, 0u};
        *reinterpret_cast<uint4*>(dst + t8 * 8) = z;
    }
}

// ---------------- tcgen05 GEMM 1: h = silu(x@w1^T)*(x@w3^T) ----------------
__global__ __launch_bounds__(128, 1) void gemm13_kernel(
    const __grid_constant__ CUtensorMap tmA, const __grid_constant__ CUtensorMap tmB) {
    const int e = blockIdx.z;
    const int cnt = g_counts[e];
    const int posBase = blockIdx.y * 128;
    if (posBase >= cnt) return;
    const int nBase = blockIdx.x * 256;      // interleaved row base
    const int fBaseF = blockIdx.x * 128;     // ffn col base
    const int tid = threadIdx.x, wid = tid >> 5, lid = tid & 31;

#if TC_OK
    extern __shared__ char smem_raw[];
    uint32_t sb = smem_u32(smem_raw);
    sb = (sb + 1023) & ~1023u;
    const uint32_t BAR = sb + NSTG * STAGE_BYTES;

    if (tid == 0) {
#pragma unroll
        for (int s = 0; s < NSTG; s++) {
            mbar_init(BAR + 16 + 16 * s, 1);       // full
            mbar_init(BAR + 24 + 16 * s, 1);       // empty
        }
        mbar_init(BAR + 16 + 16 * NSTG, 1);        // done
    }
    if (wid == 0) tc_alloc(BAR, 256);
    __syncthreads();
    uint32_t tmem;
    asm volatile("ld.shared.b32 %0, [%1];" : "=r"(tmem) : "r"(BAR));
    const uint32_t doneBar = BAR + 16 + 16 * NSTG;

    const int NT = HID / 64;      // 32
    if (tid == 0) {               // TMA producer
        int s = 0, ph = 1;
        for (int it = 0; it < NT; it++) {
            mbar_wait(BAR + 24 + 16 * s, ph);
            mbar_expect_tx(BAR + 16 + 16 * s, STAGE_BYTES);
            tma3(sb + s * STAGE_BYTES,         &tmA, it * 64, posBase, e, BAR + 16 + 16 * s);
            tma3(sb + s * STAGE_BYTES + 16384, &tmB, it * 64, nBase,   e, BAR + 16 + 16 * s);
            if (++s == NSTG) { s = 0; ph ^= 1; }
        }
    } else if (tid == 32) {       // MMA driver
        tc_fence_after();
        int s = 0, ph = 0;
        for (int it = 0; it < NT; it++) {
            mbar_wait(BAR + 16 + 16 * s, ph);
            uint64_t ad = smem_desc(sb + s * STAGE_BYTES);
            uint64_t bd = smem_desc(sb + s * STAGE_BYTES + 16384);
#pragma unroll
            for (int k = 0; k < 4; k++)
                mma_f16_ss(tmem, ad + k * 2, bd + k * 2, IDESC, (it | k) != 0);
            tc_commit(BAR + 24 + 16 * s);
            if (++s == NSTG) { s = 0; ph ^= 1; }
        }
        tc_commit(doneBar);
    }

    mbar_wait(doneBar, 0);
    tc_fence_after();

    const int p = posBase + wid * 32 + lid;
    __half* dst = g_h + ((size_t)e * TOK + p) * FFN + fBaseF;
#pragma unroll
    for (int c = 0; c < 8; c++) {
        uint32_t r[32];
        LDTM32(r, tmem + c * 32);
        tc_wait_ld();
        uint4 u0, u1;
        if (p < cnt) {
            unsigned o[8];
#pragma unroll
            for (int j = 0; j < 8; j++) {
                float a0 = __uint_as_float(r[4 * j + 0]);
                float b0 = __uint_as_float(r[4 * j + 1]);
                float a1 = __uint_as_float(r[4 * j + 2]);
                float b1 = __uint_as_float(r[4 * j + 3]);
                float v0 = (a0 / (1.f + __expf(-a0))) * b0;
                float v1 = (a1 / (1.f + __expf(-a1))) * b1;
                __half2 hh = __floats2half2_rn(v0, v1);
                o[j] = *(unsigned*)&hh;
            }
            u0 = make_uint4(o[0], o[1], o[2], o[3]);
            u1 = make_uint4(o[4], o[5], o[6], o[7]);
        } else {
            u0 = make_uint4(0, 0, 0, 0);
            u1 = make_uint4(0, 0, 0, 0);
        }
        *reinterpret_cast<uint4*>(dst + c * 16)     = u0;
        *reinterpret_cast<uint4*>(dst + c * 16 + 8) = u1;
    }
    tc_fence_before();
    __syncthreads();
    if (wid == 0) tc_dealloc(tmem, 256);
#else
    // naive-correct fallback (runs only if the non-103a cubin is ever selected)
    const int cc = (cnt + 127) & ~127;
    for (int o = tid; o < 128 * 128; o += 128) {
        int r = o >> 7, c = o & 127;
        int p = posBase + r;
        if (p >= cc) continue;
        const __half* xr = g_xg + ((size_t)e * TOK + p) * HID;
        const __half* w1r = g_w13h + ((size_t)e * FFN * 2 + (size_t)(fBaseF + c) * 2) * HID;
        const __half* w3r = w1r + HID;
        float a = 0.f, b = 0.f;
        for (int k = 0; k < HID; k++) {
            float xv = __half2float(xr[k]);
            a += xv * __half2float(w1r[k]);
            b += xv * __half2float(w3r[k]);
        }
        float s = a / (1.f + __expf(-a));
        g_h[((size_t)e * TOK + p) * FFN + fBaseF + c] = __float2half(s * b);
    }
#endif
}

// ---------------- tcgen05 GEMM 2: y = h @ w2^T ----------------
__global__ __launch_bounds__(128, 1) void gemm2_kernel(
    const __grid_constant__ CUtensorMap tmA, const __grid_constant__ CUtensorMap tmB) {
    const int e = blockIdx.z;
    const int cnt = g_counts[e];
    const int posBase = blockIdx.y * 128;
    if (posBase >= cnt) return;
    const int nBase = blockIdx.x * 256;      // HID col base
    const int tid = threadIdx.x, wid = tid >> 5, lid = tid & 31;

#if TC_OK
    extern __shared__ char smem_raw[];
    uint32_t sb = smem_u32(smem_raw);
    sb = (sb + 1023) & ~1023u;
    const uint32_t BAR = sb + NSTG * STAGE_BYTES;

    if (tid == 0) {
#pragma unroll
        for (int s = 0; s < NSTG; s++) {
            mbar_init(BAR + 16 + 16 * s, 1);
            mbar_init(BAR + 24 + 16 * s, 1);
        }
        mbar_init(BAR + 16 + 16 * NSTG, 1);
    }
    if (wid == 0) tc_alloc(BAR, 256);
    __syncthreads();
    uint32_t tmem;
    asm volatile("ld.shared.b32 %0, [%1];" : "=r"(tmem) : "r"(BAR));
    const uint32_t doneBar = BAR + 16 + 16 * NSTG;

    const int NT = FFN / 64;      // 88
    if (tid == 0) {
        int s = 0, ph = 1;
        for (int it = 0; it < NT; it++) {
            mbar_wait(BAR + 24 + 16 * s, ph);
            mbar_expect_tx(BAR + 16 + 16 * s, STAGE_BYTES);
            tma3(sb + s * STAGE_BYTES,         &tmA, it * 64, posBase, e, BAR + 16 + 16 * s);
            tma3(sb + s * STAGE_BYTES + 16384, &tmB, it * 64, nBase,   e, BAR + 16 + 16 * s);
            if (++s == NSTG) { s = 0; ph ^= 1; }
        }
    } else if (tid == 32) {
        tc_fence_after();
        int s = 0, ph = 0;
        for (int it = 0; it < NT; it++) {
            mbar_wait(BAR + 16 + 16 * s, ph);
            uint64_t ad = smem_desc(sb + s * STAGE_BYTES);
            uint64_t bd = smem_desc(sb + s * STAGE_BYTES + 16384);
#pragma unroll
            for (int k = 0; k < 4; k++)
                mma_f16_ss(tmem, ad + k * 2, bd + k * 2, IDESC, (it | k) != 0);
            tc_commit(BAR + 24 + 16 * s);
            if (++s == NSTG) { s = 0; ph ^= 1; }
        }
        tc_commit(doneBar);
    }

    mbar_wait(doneBar, 0);
    tc_fence_after();

    const int p = posBase + wid * 32 + lid;
    float* dst = g_y + ((size_t)e * TOK + p) * HID + nBase;
#pragma unroll
    for (int c = 0; c < 8; c++) {
        uint32_t r[32];
        LDTM32(r, tmem + c * 32);
        tc_wait_ld();
        if (p < cnt) {
#pragma unroll
            for (int j = 0; j < 8; j++) {
                float4 f = make_float4(__uint_as_float(r[4 * j]), __uint_as_float(r[4 * j + 1]),
                                       __uint_as_float(r[4 * j + 2]), __uint_as_float(r[4 * j + 3]));
                reinterpret_cast<float4*>(dst + c * 32)[j] = f;
            }
        }
    }
    tc_fence_before();
    __syncthreads();
    if (wid == 0) tc_dealloc(tmem, 256);
#else
    for (int o = tid; o < 128 * 256; o += 128) {
        int r = o >> 8, c = o & 255;
        int p = posBase + r;
        if (p >= cnt) continue;
        const __half* hr = g_h + ((size_t)e * TOK + p) * FFN;
        const __half* wr = g_w2h + ((size_t)e * HID + nBase + c) * FFN;
        float a = 0.f;
        for (int k = 0; k < FFN; k++) a += __half2float(hr[k]) * __half2float(wr[k]);
        g_y[((size_t)e * TOK + p) * HID + nBase + c] = a;
    }
#endif
}

// ---------------- combine ----------------
__global__ void combine_kernel(float* __restrict__ out) {
    int v = blockIdx.x * blockDim.x + threadIdx.x;
    int t  = v >> 9;
    int dv = v & 511;
    float w0 = g_wt[2 * t], w1 = g_wt[2 * t + 1];
    int s0 = g_slot[2 * t], s1 = g_slot[2 * t + 1];
    float4 a = reinterpret_cast<const float4*>(g_y + (size_t)s0 * HID)[dv];
    float4 b = reinterpret_cast<const float4*>(g_y + (size_t)s1 * HID)[dv];
    float4 r;
    r.x = w0 * a.x + w1 * b.x;
    r.y = w0 * a.y + w1 * b.y;
    r.z = w0 * a.z + w1 * b.z;
    r.w = w0 * a.w + w1 * b.w;
    reinterpret_cast<float4*>(out)[v] = r;
}

// ---------------- host ----------------
typedef CUresult (*PFN_encode)(CUtensorMap*, CUtensorMapDataType, cuuint32_t, void*,
                               const cuuint64_t*, const cuuint64_t*, const cuuint32_t*,
                               const cuuint32_t*, CUtensorMapInterleave, CUtensorMapSwizzle,
                               CUtensorMapL2promotion, CUtensorMapFloatOOBfill);

static CUtensorMap s_tmA13, s_tmB13, s_tmA2, s_tmB2;
static bool s_init = false;

static void encode_map(PFN_encode enc, CUtensorMap* tm, void* ptr,
                       uint64_t d0, uint64_t d1, uint64_t d2, uint32_t boxRows) {
    cuuint64_t dims[3]    = { d0, d1, d2 };
    cuuint64_t strides[2] = { d0 * 2, d0 * d1 * 2 };
    cuuint32_t box[3]     = { 64, boxRows, 1 };
    cuuint32_t es[3]      = { 1, 1, 1 };
    enc(tm, CU_TENSOR_MAP_DATA_TYPE_FLOAT16, 3, ptr, dims, strides, box, es,
        CU_TENSOR_MAP_INTERLEAVE_NONE, CU_TENSOR_MAP_SWIZZLE_128B,
        CU_TENSOR_MAP_L2_PROMOTION_L2_128B, CU_TENSOR_MAP_FLOAT_OOB_FILL_NONE);
}

extern "C" void kernel_launch(void* const* d_in, const int* in_sizes, int n_in,
                              void* d_out, int out_size) {
    const float* x  = (const float*)d_in[0];
    const float* wg = (const float*)d_in[1];
    const float* w1 = (const float*)d_in[2];
    const float* w2 = (const float*)d_in[3];
    const float* w3 = (const float*)d_in[4];
    float* out = (float*)d_out;

    if (!s_init) {
        void* fn = nullptr;
        cudaDriverEntryPointQueryResult qr;
        cudaGetDriverEntryPoint("cuTensorMapEncodeTiled", &fn, cudaEnableDefault, &qr);
        PFN_encode enc = (PFN_encode)fn;
        void *pxg, *pw13, *pw2, *ph;
        cudaGetSymbolAddress(&pxg,  g_xg);
        cudaGetSymbolAddress(&pw13, g_w13h);
        cudaGetSymbolAddress(&pw2,  g_w2h);
        cudaGetSymbolAddress(&ph,   g_h);
        encode_map(enc, &s_tmA13, pxg,  HID, TOK,     NEXP, 128);
        encode_map(enc, &s_tmB13, pw13, HID, 2 * FFN, NEXP, 256);
        encode_map(enc, &s_tmA2,  ph,   FFN, TOK,     NEXP, 128);
        encode_map(enc, &s_tmB2,  pw2,  FFN, HID,     NEXP, 256);
        cudaFuncSetAttribute(gemm13_kernel, cudaFuncAttributeMaxDynamicSharedMemorySize, SMEM_REQ);
        cudaFuncSetAttribute(gemm2_kernel,  cudaFuncAttributeMaxDynamicSharedMemorySize, SMEM_REQ);
        s_init = true;
    }

    zero_counts_kernel<<<1, 32>>>();
    router_kernel<<<(TOK * 32) / 256, 256>>>(x, wg);
    gather_kernel<<<dim3(TOK, NEXP), 256>>>(x);
    conv_w13_kernel<<<dim3(FFN * 2 * (HID / 8) / 256, 1, NEXP), 256>>>(w1, w3);
    conv_w2_kernel<<<dim3(HID * (FFN / 8) / 256, 1, NEXP), 256>>>(w2);
    gemm13_kernel<<<dim3(2 * FFN / 256, TOK / 128, NEXP), 128, SMEM_REQ>>>(s_tmA13, s_tmB13);
    gemm2_kernel<<<dim3(HID / 256, TOK / 128, NEXP), 128, SMEM_REQ>>>(s_tmA2, s_tmB2);
    combine_kernel<<<(TOK * HID / 4) / 256, 256>>>(out);
}